// round 16
// baseline (speedup 1.0000x reference)
#include <cuda_runtime.h>
#include <cuda_fp16.h>
#include <cstdint>

#define B_   16
#define C_   256
#define SEQ_ 4096
#define NQKV 768

// ---------------- scratch (static device globals) ---------------------------
__device__ __half g_xh [(size_t)B_ * C_ * SEQ_];   // x fp16 [b][k][s]
__device__ __half g_wh [(size_t)C_ * NQKV];        // Wqkv fp16 [k][768]
__device__ __half g_woh[(size_t)C_ * C_];          // Wo fp16 [k][n]
__device__ __half g_qkv[(size_t)B_ * SEQ_ * NQKV]; // fp16 [b][s][768]
__device__ __half g_ah [(size_t)B_ * SEQ_ * C_];   // attn out fp16 [b][s][k]

// ---------------- PTX helpers ------------------------------------------------
__device__ __forceinline__ void mma_f16(float* acc, const uint32_t* a,
                                        const uint32_t* b) {
    asm volatile(
        "mma.sync.aligned.m16n8k16.row.col.f32.f16.f16.f32 "
        "{%0,%1,%2,%3}, {%4,%5,%6,%7}, {%8,%9}, {%0,%1,%2,%3};"
        : "+f"(acc[0]), "+f"(acc[1]), "+f"(acc[2]), "+f"(acc[3])
        : "r"(a[0]), "r"(a[1]), "r"(a[2]), "r"(a[3]), "r"(b[0]), "r"(b[1]));
}
__device__ __forceinline__ void ldsm4(uint32_t* r, uint32_t addr) {
    asm volatile("ldmatrix.sync.aligned.m8n8.x4.shared.b16 {%0,%1,%2,%3}, [%4];"
        : "=r"(r[0]), "=r"(r[1]), "=r"(r[2]), "=r"(r[3]) : "r"(addr));
}
__device__ __forceinline__ void ldsm4t(uint32_t* r, uint32_t addr) {
    asm volatile("ldmatrix.sync.aligned.m8n8.x4.trans.shared.b16 {%0,%1,%2,%3}, [%4];"
        : "=r"(r[0]), "=r"(r[1]), "=r"(r[2]), "=r"(r[3]) : "r"(addr));
}
__device__ __forceinline__ void cpa16(uint32_t dst, const void* src) {
    asm volatile("cp.async.cg.shared.global [%0], [%1], 16;" :: "r"(dst), "l"(src));
}
#define CP_COMMIT()  asm volatile("cp.async.commit_group;")
#define CP_WAIT1()   asm volatile("cp.async.wait_group 1;")
#define CP_WAIT2()   asm volatile("cp.async.wait_group 2;")

// ============================================================================
// Conversion passes
// ============================================================================
__global__ void conv_f4(const float4* __restrict__ in, uint2* __restrict__ oh,
                        int n4)
{
    int i = blockIdx.x * 256 + threadIdx.x;
    if (i >= n4) return;
    float4 v = in[i];
    __half2 h01 = __floats2half2_rn(v.x, v.y);
    __half2 h23 = __floats2half2_rn(v.z, v.w);
    uint2 o;
    o.x = *(uint32_t*)&h01; o.y = *(uint32_t*)&h23;
    oh[i] = o;
}

__global__ void conv_wqkv(const float* __restrict__ wq,
                          const float* __restrict__ wkv)
{
    int idx = blockIdx.x * 256 + threadIdx.x;      // 256*768
    int k = idx / NQKV, n = idx % NQKV;
    float f = (n < 256) ? wq[k * 256 + n] : wkv[k * 512 + (n - 256)];
    g_wh[idx] = __float2half_rn(f);
}

// ============================================================================
// GEMM1 (fp16, 1-term): qkv[b,s,n] = sum_k x[b,k,s]*W[k,n] + bias[n]
//   128x128 block, BK=32, 8 warps (2x4), 4-stage cp.async pipeline.
// ============================================================================
#define G1_ST 16384

__global__ __launch_bounds__(256) void gemm_qkv_mma(
    const float* __restrict__ bq, const float* __restrict__ bkv, int b0)
{
    extern __shared__ __align__(16) char smem[];
    uint32_t sb = (uint32_t)__cvta_generic_to_shared(smem);

    int b  = b0 + blockIdx.z;
    int n0 = blockIdx.x * 128;
    int s0 = blockIdx.y * 128;
    const __half* xb = g_xh + (size_t)b * C_ * SEQ_;

    int tid = threadIdx.x, warp = tid >> 5, lane = tid & 31;
    int g = lane >> 2, tg = lane & 3;
    int wm = (warp & 1) * 64, wn = (warp >> 1) * 32;

    float acc[4][4][4];
    #pragma unroll
    for (int i = 0; i < 4; i++)
        #pragma unroll
        for (int j = 0; j < 4; j++)
            #pragma unroll
            for (int q = 0; q < 4; q++) acc[i][j][q] = 0.f;

    auto fill = [&](uint32_t st, int kt) {
        int k0 = kt * 32;
        #pragma unroll
        for (int i = 0; i < 2; i++) {
            int idx2 = (i << 8) + tid;
            int row = idx2 >> 4, ch = idx2 & 15;
            uint32_t doff = row * 256 + ((ch ^ (row & 7)) << 4);
            cpa16(st + doff, xb + (size_t)(k0 + row) * SEQ_ + s0 + ch * 8);
            cpa16(st + 8192 + doff,
                  g_wh + (size_t)(k0 + row) * NQKV + n0 + ch * 8);
        }
    };

    fill(sb,              0); CP_COMMIT();
    fill(sb + G1_ST,      1); CP_COMMIT();
    fill(sb + 2 * G1_ST,  2); CP_COMMIT();

    for (int kt = 0; kt < 8; kt++) {
        CP_WAIT2();
        __syncthreads();
        if (kt < 5) fill(sb + ((kt + 3) & 3) * G1_ST, kt + 3);
        CP_COMMIT();

        uint32_t sA = sb + (kt & 3) * G1_ST;
        #pragma unroll
        for (int ks = 0; ks < 2; ks++) {
            int row = ks * 16 + (lane & 7) + ((lane >> 4) << 3);
            int chs = (lane >> 3) & 1;
            int rx  = row & 7;
            uint32_t rowoff = row * 256;

            uint32_t ah[4][4];
            #pragma unroll
            for (int mt = 0; mt < 4; mt++) {
                int ch = ((wm + mt * 16) >> 3) + chs;
                ldsm4t(ah[mt], sA + rowoff + ((ch ^ rx) << 4));
            }
            uint32_t bh[4][2];
            #pragma unroll
            for (int p = 0; p < 2; p++) {
                int ch = ((wn + p * 16) >> 3) + chs;
                uint32_t r[4];
                ldsm4t(r, sA + 8192 + rowoff + ((ch ^ rx) << 4));
                bh[2*p][0] = r[0];   bh[2*p][1] = r[2];
                bh[2*p+1][0] = r[1]; bh[2*p+1][1] = r[3];
            }
            #pragma unroll
            for (int mt = 0; mt < 4; mt++)
                #pragma unroll
                for (int nt = 0; nt < 4; nt++)
                    mma_f16(acc[mt][nt], ah[mt], bh[nt]);
        }
    }

    #pragma unroll
    for (int nt = 0; nt < 4; nt++) {
        int nglob = n0 + wn + nt * 8 + 2 * tg;
        float b0f = (nglob < 256) ? bq[nglob]     : bkv[nglob - 256];
        float b1f = (nglob < 256) ? bq[nglob + 1] : bkv[nglob - 255];
        #pragma unroll
        for (int mt = 0; mt < 4; mt++) {
            int s = s0 + wm + mt * 16 + g;
            size_t r0 = ((size_t)b * SEQ_ + s) * NQKV + nglob;
            size_t r1 = r0 + (size_t)8 * NQKV;
            *(__half2*)(g_qkv + r0) =
                __floats2half2_rn(acc[mt][nt][0] + b0f, acc[mt][nt][1] + b1f);
            *(__half2*)(g_qkv + r1) =
                __floats2half2_rn(acc[mt][nt][2] + b0f, acc[mt][nt][3] + b1f);
        }
    }
}

// ============================================================================
// Attention: per token, 4x4 over heads. One warp per token.
//   Lane l owns dims {2l, 2l+1} -> all q/k/v traffic is half2 (4B/lane).
// ============================================================================
__global__ __launch_bounds__(256) void attn_kernel(int b0)
{
    int warp = threadIdx.x >> 5, l = threadIdx.x & 31;
    int t = b0 * SEQ_ + blockIdx.x * 8 + warp;
    const __half* base = g_qkv + (size_t)t * NQKV;

    float2 q2[4], k2[4];
    #pragma unroll
    for (int n = 0; n < 4; n++) {
        q2[n] = __half22float2(*(const __half2*)(base + n * 64 + 2 * l));
        k2[n] = __half22float2(*(const __half2*)(base + 256 + n * 64 + 2 * l));
    }
    float s[16];
    #pragma unroll
    for (int n = 0; n < 4; n++)
        #pragma unroll
        for (int m = 0; m < 4; m++)
            s[n * 4 + m] = q2[n].x * k2[m].x + q2[n].y * k2[m].y;
    #pragma unroll
    for (int off = 16; off > 0; off >>= 1)
        #pragma unroll
        for (int i = 0; i < 16; i++)
            s[i] += __shfl_xor_sync(0xffffffffu, s[i], off);

    float w[16];
    #pragma unroll
    for (int n = 0; n < 4; n++) {
        float p0 = s[n*4+0] * 0.125f, p1 = s[n*4+1] * 0.125f;
        float p2 = s[n*4+2] * 0.125f, p3 = s[n*4+3] * 0.125f;
        float mx = fmaxf(fmaxf(p0, p1), fmaxf(p2, p3));
        float e0 = __expf(p0 - mx), e1 = __expf(p1 - mx);
        float e2 = __expf(p2 - mx), e3 = __expf(p3 - mx);
        float inv = 1.0f / (e0 + e1 + e2 + e3);
        w[n*4+0] = e0 * inv; w[n*4+1] = e1 * inv;
        w[n*4+2] = e2 * inv; w[n*4+3] = e3 * inv;
    }
    float ox[4] = {0.f,0.f,0.f,0.f}, oy[4] = {0.f,0.f,0.f,0.f};
    #pragma unroll
    for (int m = 0; m < 4; m++) {
        float2 v2 = __half22float2(*(const __half2*)(base + 512 + m * 64 + 2 * l));
        #pragma unroll
        for (int n = 0; n < 4; n++) {
            ox[n] += w[n * 4 + m] * v2.x;
            oy[n] += w[n * 4 + m] * v2.y;
        }
    }
    size_t d = (size_t)t * C_;
    #pragma unroll
    for (int n = 0; n < 4; n++)
        *(__half2*)(g_ah + d + n * 64 + 2 * l) = __floats2half2_rn(ox[n], oy[n]);
}

// ============================================================================
// GEMM2 (fp16, 1-term, fused transpose): out[b,n,s] = sum_k attn[b,s,k]*wo[k,n]+bo[n]
//   128x128 block, BK=64, 2 stages x 32KB.
// ============================================================================
__global__ __launch_bounds__(256) void gemm_out_mma(
    const float* __restrict__ bo, float* __restrict__ out, int b0)
{
    extern __shared__ __align__(16) char smem[];
    uint32_t sb = (uint32_t)__cvta_generic_to_shared(smem);

    int b  = b0 + blockIdx.z;
    int n0 = blockIdx.x * 128;
    int s0 = blockIdx.y * 128;
    const __half* ah_b = g_ah + (size_t)b * SEQ_ * C_;

    int tid = threadIdx.x, warp = tid >> 5, lane = tid & 31;
    int g = lane >> 2, tg = lane & 3;
    int wm = (warp & 1) * 64, wn = (warp >> 1) * 32;

    float acc[4][4][4];
    #pragma unroll
    for (int i = 0; i < 4; i++)
        #pragma unroll
        for (int j = 0; j < 4; j++)
            #pragma unroll
            for (int q = 0; q < 4; q++) acc[i][j][q] = 0.f;

    auto fill = [&](uint32_t st, int k0) {
        #pragma unroll
        for (int i = 0; i < 4; i++) {
            int idx2 = (i << 8) + tid;
            int rowA = idx2 >> 3, chA = idx2 & 7;
            uint32_t dA = rowA * 128 + ((chA ^ (rowA & 7)) << 4);
            cpa16(st + dA, ah_b + (size_t)(s0 + rowA) * C_ + k0 + chA * 8);
            int rowB = idx2 >> 4, chB = idx2 & 15;
            uint32_t dB = rowB * 256 + ((chB ^ (rowB & 7)) << 4);
            cpa16(st + 16384 + dB,
                  g_woh + (size_t)(k0 + rowB) * C_ + n0 + chB * 8);
        }
    };

    fill(sb, 0);          CP_COMMIT();
    fill(sb + 32768, 64); CP_COMMIT();

    for (int kt = 0; kt < 4; kt++) {
        CP_WAIT1();
        __syncthreads();
        uint32_t sA = sb + (kt & 1) * 32768;
        uint32_t sB = sA + 16384;

        #pragma unroll
        for (int ks = 0; ks < 4; ks++) {
            uint32_t ah[4][4];
            #pragma unroll
            for (int mt = 0; mt < 4; mt++) {
                int row = wm + mt * 16 + (lane & 15);
                int ch  = ks * 2 + (lane >> 4);
                ldsm4(ah[mt], sA + row * 128 + ((ch ^ (row & 7)) << 4));
            }
            int rowb = ks * 16 + (lane & 7) + ((lane >> 4) << 3);
            int chs  = (lane >> 3) & 1;
            int rx   = rowb & 7;
            uint32_t rowoff = rowb * 256;
            uint32_t bh[4][2];
            #pragma unroll
            for (int p = 0; p < 2; p++) {
                int ch = ((wn + p * 16) >> 3) + chs;
                uint32_t r[4];
                ldsm4t(r, sB + rowoff + ((ch ^ rx) << 4));
                bh[2*p][0] = r[0];   bh[2*p][1] = r[2];
                bh[2*p+1][0] = r[1]; bh[2*p+1][1] = r[3];
            }
            #pragma unroll
            for (int mt = 0; mt < 4; mt++)
                #pragma unroll
                for (int nt = 0; nt < 4; nt++)
                    mma_f16(acc[mt][nt], ah[mt], bh[nt]);
        }
        __syncthreads();
        if (kt < 2)
            fill(sb + (kt & 1) * 32768, (kt + 2) * 64);
        CP_COMMIT();
    }

    float* ob = out + (size_t)b * C_ * SEQ_;
    #pragma unroll
    for (int nt = 0; nt < 4; nt++) {
        int c = n0 + wn + nt * 8 + 2 * tg;
        float b0f = bo[c], b1f = bo[c + 1];
        #pragma unroll
        for (int mt = 0; mt < 4; mt++) {
            int s = s0 + wm + mt * 16 + g;
            ob[(size_t)c       * SEQ_ + s]     = acc[mt][nt][0] + b0f;
            ob[(size_t)(c + 1) * SEQ_ + s]     = acc[mt][nt][1] + b1f;
            ob[(size_t)c       * SEQ_ + s + 8] = acc[mt][nt][2] + b0f;
            ob[(size_t)(c + 1) * SEQ_ + s + 8] = acc[mt][nt][3] + b1f;
        }
    }
}

// ============================================================================
extern "C" void kernel_launch(void* const* d_in, const int* in_sizes, int n_in,
                              void* d_out, int out_size)
{
    const float* x   = (const float*)d_in[0];
    const float* wq  = (const float*)d_in[1];
    const float* bq  = (const float*)d_in[2];
    const float* wkv = (const float*)d_in[3];
    const float* bkv = (const float*)d_in[4];
    const float* wo  = (const float*)d_in[5];
    const float* bo  = (const float*)d_in[6];
    float* out = (float*)d_out;

    static cudaStream_t s[2];
    static cudaEvent_t evFork, evC0, evA, evB1, evJoin[2];
    static bool init_done = false;
    if (!init_done) {
        cudaFuncSetAttribute(gemm_qkv_mma,
            cudaFuncAttributeMaxDynamicSharedMemorySize, 4 * G1_ST);
        cudaFuncSetAttribute(gemm_out_mma,
            cudaFuncAttributeMaxDynamicSharedMemorySize, 65536);
        cudaStreamCreateWithFlags(&s[0], cudaStreamNonBlocking);
        cudaStreamCreateWithFlags(&s[1], cudaStreamNonBlocking);
        cudaEventCreateWithFlags(&evFork,    cudaEventDisableTiming);
        cudaEventCreateWithFlags(&evC0,      cudaEventDisableTiming);
        cudaEventCreateWithFlags(&evA,       cudaEventDisableTiming);
        cudaEventCreateWithFlags(&evB1,      cudaEventDisableTiming);
        cudaEventCreateWithFlags(&evJoin[0], cudaEventDisableTiming);
        cudaEventCreateWithFlags(&evJoin[1], cudaEventDisableTiming);
        init_done = true;
    }

    __half *xh, *woh;
    cudaGetSymbolAddress((void**)&xh,  g_xh);
    cudaGetSymbolAddress((void**)&woh, g_woh);

    // small weight convs on the capture (default) stream
    int nw4 = (C_ * C_) / 4;
    conv_f4<<<(nw4 + 255) / 256, 256>>>((const float4*)wo, (uint2*)woh, nw4);
    conv_wqkv<<<(C_ * NQKV) / 256, 256>>>(wq, wkv);

    // fork
    cudaEventRecord(evFork, 0);
    cudaStreamWaitEvent(s[0], evFork, 0);
    cudaStreamWaitEvent(s[1], evFork, 0);

    const size_t bat4 = (size_t)C_ * SEQ_ / 4;   // float4s per batch
    const int n4half = (int)(8 * bat4);

    // NOTE: host enqueue order below is a topological order of the event DAG —
    // every cudaEventRecord precedes any cudaStreamWaitEvent on that event
    // (required for stream capture).

    // -- stage 1 (s0): conv(b0-7) -> [evC0] -> G1(b0-7) -> [evA]
    conv_f4<<<(n4half + 255) / 256, 256, 0, s[0]>>>(
        (const float4*)x, (uint2*)xh, n4half);
    cudaEventRecord(evC0, s[0]);
    gemm_qkv_mma<<<dim3(6, 32, 8), 256, 4 * G1_ST, s[0]>>>(bq, bkv, 0);
    cudaEventRecord(evA, s[0]);

    // -- stage 2 (s1): wait evC0 -> conv(b8-15) -> wait evA ->
    //                  G1(b8-11) -> [evB1] -> G1(b12-15)
    cudaStreamWaitEvent(s[1], evC0, 0);
    conv_f4<<<(n4half + 255) / 256, 256, 0, s[1]>>>(
        (const float4*)x + 8 * bat4, (uint2*)xh + 8 * bat4, n4half);
    cudaStreamWaitEvent(s[1], evA, 0);
    gemm_qkv_mma<<<dim3(6, 32, 4), 256, 4 * G1_ST, s[1]>>>(bq, bkv, 8);
    cudaEventRecord(evB1, s[1]);
    gemm_qkv_mma<<<dim3(6, 32, 4), 256, 4 * G1_ST, s[1]>>>(bq, bkv, 12);

    // -- stage 3 (s0): epi(b0-7) -> wait evB1 -> epi(b8-11)
    attn_kernel<<<(8 * SEQ_) / 8, 256, 0, s[0]>>>(0);
    gemm_out_mma<<<dim3(2, 32, 8), 256, 65536, s[0]>>>(bo, out, 0);
    cudaStreamWaitEvent(s[0], evB1, 0);
    attn_kernel<<<(4 * SEQ_) / 8, 256, 0, s[0]>>>(8);
    gemm_out_mma<<<dim3(2, 32, 4), 256, 65536, s[0]>>>(bo, out, 8);

    // -- stage 4 (s1): epi(b12-15)
    attn_kernel<<<(4 * SEQ_) / 8, 256, 0, s[1]>>>(12);
    gemm_out_mma<<<dim3(2, 32, 4), 256, 65536, s[1]>>>(bo, out, 12);

    // join back to the capture stream
    cudaEventRecord(evJoin[0], s[0]);
    cudaEventRecord(evJoin[1], s[1]);
    cudaStreamWaitEvent(0, evJoin[0], 0);
    cudaStreamWaitEvent(0, evJoin[1], 0);
}

// round 17
// speedup vs baseline: 1.0165x; 1.0165x over previous
#include <cuda_runtime.h>
#include <cuda_fp16.h>
#include <cstdint>

#define B_   16
#define C_   256
#define SEQ_ 4096
#define NQKV 768
#define GRP  8          // batches per pipeline group
#define NGRP (B_ / GRP) // 2 groups, one per stream

// ---------------- scratch (static device globals) ---------------------------
__device__ __half g_wh [(size_t)C_ * NQKV];        // Wqkv fp16 [k][768]
__device__ __half g_woh[(size_t)C_ * C_];          // Wo fp16 [k][n]
__device__ __half g_qkv[(size_t)B_ * SEQ_ * NQKV]; // fp16 [b][s][768]
__device__ __half g_ah [(size_t)B_ * SEQ_ * C_];   // attn out fp16 [b][s][k]

// ---------------- PTX helpers ------------------------------------------------
__device__ __forceinline__ void mma_f16(float* acc, const uint32_t* a,
                                        const uint32_t* b) {
    asm volatile(
        "mma.sync.aligned.m16n8k16.row.col.f32.f16.f16.f32 "
        "{%0,%1,%2,%3}, {%4,%5,%6,%7}, {%8,%9}, {%0,%1,%2,%3};"
        : "+f"(acc[0]), "+f"(acc[1]), "+f"(acc[2]), "+f"(acc[3])
        : "r"(a[0]), "r"(a[1]), "r"(a[2]), "r"(a[3]), "r"(b[0]), "r"(b[1]));
}
__device__ __forceinline__ void ldsm4(uint32_t* r, uint32_t addr) {
    asm volatile("ldmatrix.sync.aligned.m8n8.x4.shared.b16 {%0,%1,%2,%3}, [%4];"
        : "=r"(r[0]), "=r"(r[1]), "=r"(r[2]), "=r"(r[3]) : "r"(addr));
}
__device__ __forceinline__ void ldsm4t(uint32_t* r, uint32_t addr) {
    asm volatile("ldmatrix.sync.aligned.m8n8.x4.trans.shared.b16 {%0,%1,%2,%3}, [%4];"
        : "=r"(r[0]), "=r"(r[1]), "=r"(r[2]), "=r"(r[3]) : "r"(addr));
}
__device__ __forceinline__ void cpa16(uint32_t dst, const void* src) {
    asm volatile("cp.async.cg.shared.global [%0], [%1], 16;" :: "r"(dst), "l"(src));
}
#define CP_COMMIT()  asm volatile("cp.async.commit_group;")
#define CP_WAIT1()   asm volatile("cp.async.wait_group 1;")

// ============================================================================
// Conversion passes (weights only; x conversion is fused into GEMM1)
// ============================================================================
__global__ void conv_f4(const float4* __restrict__ in, uint2* __restrict__ oh,
                        int n4)
{
    int i = blockIdx.x * 256 + threadIdx.x;
    if (i >= n4) return;
    float4 v = in[i];
    __half2 h01 = __floats2half2_rn(v.x, v.y);
    __half2 h23 = __floats2half2_rn(v.z, v.w);
    uint2 o;
    o.x = *(uint32_t*)&h01; o.y = *(uint32_t*)&h23;
    oh[i] = o;
}

__global__ void conv_wqkv(const float* __restrict__ wq,
                          const float* __restrict__ wkv)
{
    int idx = blockIdx.x * 256 + threadIdx.x;      // 256*768
    int k = idx / NQKV, n = idx % NQKV;
    float f = (n < 256) ? wq[k * 256 + n] : wkv[k * 512 + (n - 256)];
    g_wh[idx] = __float2half_rn(f);
}

// ============================================================================
// GEMM1 (fp16, 1-term, fused x-conversion):
//   qkv[b,s,n] = sum_k x[b,k,s]*W[k,n] + bias[n]
//   128x128 block, BK=32, 8 warps (2x4). 2 stages x (A 8KB + B 8KB).
//   A: fp32 LDG.128 -> cvt -> STS.64 into swizzled layout (LDG issued at
//      stage top, lands under MMAs; STS after the post-MMA sync).
//   B: cp.async fp16 double-buffered.
// ============================================================================
#define G1_ST 16384

__global__ __launch_bounds__(256, 2) void gemm_qkv_mma(
    const float* __restrict__ x,
    const float* __restrict__ bq, const float* __restrict__ bkv, int b0)
{
    extern __shared__ __align__(16) char smem[];
    uint32_t sb = (uint32_t)__cvta_generic_to_shared(smem);

    int b  = b0 + blockIdx.z;
    int n0 = blockIdx.x * 128;
    int s0 = blockIdx.y * 128;
    const float* xb = x + (size_t)b * C_ * SEQ_;

    int tid = threadIdx.x, warp = tid >> 5, lane = tid & 31;
    int g = lane >> 2, tg = lane & 3;
    int wm = (warp & 1) * 64, wn = (warp >> 1) * 32;

    float acc[4][4][4];
    #pragma unroll
    for (int i = 0; i < 4; i++)
        #pragma unroll
        for (int j = 0; j < 4; j++)
            #pragma unroll
            for (int q = 0; q < 4; q++) acc[i][j][q] = 0.f;

    // per-thread A coords: 4 units of 8B (4 fp32 -> 4 fp16)
    int rA[4], chA[4], hfA[4];
    #pragma unroll
    for (int i = 0; i < 4; i++) {
        int idx = tid + i * 256;          // 0..1023
        rA[i]  = idx >> 5;                // k-row 0..31
        chA[i] = (idx & 31) >> 1;         // 16B chunk 0..15
        hfA[i] = idx & 1;                 // half of chunk
    }

    auto ldgA = [&](float4* v, int kt) {
        int k0 = kt * 32;
        #pragma unroll
        for (int i = 0; i < 4; i++)
            v[i] = *(const float4*)(xb + (size_t)(k0 + rA[i]) * SEQ_ +
                                    s0 + chA[i] * 8 + hfA[i] * 4);
    };
    auto stsA = [&](uint32_t st, const float4* v) {
        #pragma unroll
        for (int i = 0; i < 4; i++) {
            uint32_t doff = rA[i] * 256 + ((chA[i] ^ (rA[i] & 7)) << 4)
                          + hfA[i] * 8;
            __half2 h01 = __floats2half2_rn(v[i].x, v[i].y);
            __half2 h23 = __floats2half2_rn(v[i].z, v[i].w);
            asm volatile("st.shared.v2.u32 [%0], {%1, %2};"
                :: "r"(st + doff),
                   "r"(*(uint32_t*)&h01), "r"(*(uint32_t*)&h23));
        }
    };
    auto fillB = [&](uint32_t st, int kt) {
        int k0 = kt * 32;
        #pragma unroll
        for (int i = 0; i < 2; i++) {
            int idx = tid + i * 256;
            int row = idx >> 4, ch = idx & 15;
            uint32_t doff = row * 256 + ((ch ^ (row & 7)) << 4);
            cpa16(st + 8192 + doff,
                  g_wh + (size_t)(k0 + row) * NQKV + n0 + ch * 8);
        }
    };

    // prologue: stages 0 and 1
    float4 av[4];
    ldgA(av, 0); stsA(sb, av);
    ldgA(av, 1); stsA(sb + G1_ST, av);
    fillB(sb, 0);         CP_COMMIT();
    fillB(sb + G1_ST, 1); CP_COMMIT();

    for (int kt = 0; kt < 8; kt++) {
        CP_WAIT1();
        __syncthreads();
        uint32_t sA = sb + (kt & 1) * G1_ST;

        if (kt + 2 < 8) ldgA(av, kt + 2);   // hides under MMAs

        #pragma unroll
        for (int ks = 0; ks < 2; ks++) {
            int row = ks * 16 + (lane & 7) + ((lane >> 4) << 3);
            int chs = (lane >> 3) & 1;
            int rx  = row & 7;
            uint32_t rowoff = row * 256;

            uint32_t ah[4][4];
            #pragma unroll
            for (int mt = 0; mt < 4; mt++) {
                int ch = ((wm + mt * 16) >> 3) + chs;
                ldsm4t(ah[mt], sA + rowoff + ((ch ^ rx) << 4));
            }
            uint32_t bh[4][2];
            #pragma unroll
            for (int p = 0; p < 2; p++) {
                int ch = ((wn + p * 16) >> 3) + chs;
                uint32_t r[4];
                ldsm4t(r, sA + 8192 + rowoff + ((ch ^ rx) << 4));
                bh[2*p][0] = r[0];   bh[2*p][1] = r[2];
                bh[2*p+1][0] = r[1]; bh[2*p+1][1] = r[3];
            }
            #pragma unroll
            for (int mt = 0; mt < 4; mt++)
                #pragma unroll
                for (int nt = 0; nt < 4; nt++)
                    mma_f16(acc[mt][nt], ah[mt], bh[nt]);
        }
        __syncthreads();
        if (kt + 2 < 8) {
            stsA(sA, av);        // stage (kt&1) now free, becomes kt+2
            fillB(sA, kt + 2);
        }
        CP_COMMIT();
    }

    #pragma unroll
    for (int nt = 0; nt < 4; nt++) {
        int nglob = n0 + wn + nt * 8 + 2 * tg;
        float b0f = (nglob < 256) ? bq[nglob]     : bkv[nglob - 256];
        float b1f = (nglob < 256) ? bq[nglob + 1] : bkv[nglob - 255];
        #pragma unroll
        for (int mt = 0; mt < 4; mt++) {
            int s = s0 + wm + mt * 16 + g;
            size_t r0 = ((size_t)b * SEQ_ + s) * NQKV + nglob;
            size_t r1 = r0 + (size_t)8 * NQKV;
            *(__half2*)(g_qkv + r0) =
                __floats2half2_rn(acc[mt][nt][0] + b0f, acc[mt][nt][1] + b1f);
            *(__half2*)(g_qkv + r1) =
                __floats2half2_rn(acc[mt][nt][2] + b0f, acc[mt][nt][3] + b1f);
        }
    }
}

// ============================================================================
// Attention: per token, 4x4 over heads. One warp per token.
//   Lane l owns dims {2l, 2l+1} -> all q/k/v traffic is half2 (4B/lane).
// ============================================================================
__global__ __launch_bounds__(256) void attn_kernel(int b0)
{
    int warp = threadIdx.x >> 5, l = threadIdx.x & 31;
    int t = b0 * SEQ_ + blockIdx.x * 8 + warp;
    const __half* base = g_qkv + (size_t)t * NQKV;

    float2 q2[4], k2[4];
    #pragma unroll
    for (int n = 0; n < 4; n++) {
        q2[n] = __half22float2(*(const __half2*)(base + n * 64 + 2 * l));
        k2[n] = __half22float2(*(const __half2*)(base + 256 + n * 64 + 2 * l));
    }
    float s[16];
    #pragma unroll
    for (int n = 0; n < 4; n++)
        #pragma unroll
        for (int m = 0; m < 4; m++)
            s[n * 4 + m] = q2[n].x * k2[m].x + q2[n].y * k2[m].y;
    #pragma unroll
    for (int off = 16; off > 0; off >>= 1)
        #pragma unroll
        for (int i = 0; i < 16; i++)
            s[i] += __shfl_xor_sync(0xffffffffu, s[i], off);

    float w[16];
    #pragma unroll
    for (int n = 0; n < 4; n++) {
        float p0 = s[n*4+0] * 0.125f, p1 = s[n*4+1] * 0.125f;
        float p2 = s[n*4+2] * 0.125f, p3 = s[n*4+3] * 0.125f;
        float mx = fmaxf(fmaxf(p0, p1), fmaxf(p2, p3));
        float e0 = __expf(p0 - mx), e1 = __expf(p1 - mx);
        float e2 = __expf(p2 - mx), e3 = __expf(p3 - mx);
        float inv = 1.0f / (e0 + e1 + e2 + e3);
        w[n*4+0] = e0 * inv; w[n*4+1] = e1 * inv;
        w[n*4+2] = e2 * inv; w[n*4+3] = e3 * inv;
    }
    float ox[4] = {0.f,0.f,0.f,0.f}, oy[4] = {0.f,0.f,0.f,0.f};
    #pragma unroll
    for (int m = 0; m < 4; m++) {
        float2 v2 = __half22float2(*(const __half2*)(base + 512 + m * 64 + 2 * l));
        #pragma unroll
        for (int n = 0; n < 4; n++) {
            ox[n] += w[n * 4 + m] * v2.x;
            oy[n] += w[n * 4 + m] * v2.y;
        }
    }
    size_t d = (size_t)t * C_;
    #pragma unroll
    for (int n = 0; n < 4; n++)
        *(__half2*)(g_ah + d + n * 64 + 2 * l) = __floats2half2_rn(ox[n], oy[n]);
}

// ============================================================================
// GEMM2 (fp16, 1-term, fused transpose): out[b,n,s] = sum_k attn[b,s,k]*wo[k,n]+bo[n]
//   128x128 block, BK=64, 2 stages x 32KB.
// ============================================================================
__global__ __launch_bounds__(256) void gemm_out_mma(
    const float* __restrict__ bo, float* __restrict__ out, int b0)
{
    extern __shared__ __align__(16) char smem[];
    uint32_t sb = (uint32_t)__cvta_generic_to_shared(smem);

    int b  = b0 + blockIdx.z;
    int n0 = blockIdx.x * 128;
    int s0 = blockIdx.y * 128;
    const __half* ah_b = g_ah + (size_t)b * SEQ_ * C_;

    int tid = threadIdx.x, warp = tid >> 5, lane = tid & 31;
    int g = lane >> 2, tg = lane & 3;
    int wm = (warp & 1) * 64, wn = (warp >> 1) * 32;

    float acc[4][4][4];
    #pragma unroll
    for (int i = 0; i < 4; i++)
        #pragma unroll
        for (int j = 0; j < 4; j++)
            #pragma unroll
            for (int q = 0; q < 4; q++) acc[i][j][q] = 0.f;

    auto fill = [&](uint32_t st, int k0) {
        #pragma unroll
        for (int i = 0; i < 4; i++) {
            int idx2 = (i << 8) + tid;
            int rowA = idx2 >> 3, chA = idx2 & 7;
            uint32_t dA = rowA * 128 + ((chA ^ (rowA & 7)) << 4);
            cpa16(st + dA, ah_b + (size_t)(s0 + rowA) * C_ + k0 + chA * 8);
            int rowB = idx2 >> 4, chB = idx2 & 15;
            uint32_t dB = rowB * 256 + ((chB ^ (rowB & 7)) << 4);
            cpa16(st + 16384 + dB,
                  g_woh + (size_t)(k0 + rowB) * C_ + n0 + chB * 8);
        }
    };

    fill(sb, 0);          CP_COMMIT();
    fill(sb + 32768, 64); CP_COMMIT();

    for (int kt = 0; kt < 4; kt++) {
        CP_WAIT1();
        __syncthreads();
        uint32_t sA = sb + (kt & 1) * 32768;
        uint32_t sB = sA + 16384;

        #pragma unroll
        for (int ks = 0; ks < 4; ks++) {
            uint32_t ah[4][4];
            #pragma unroll
            for (int mt = 0; mt < 4; mt++) {
                int row = wm + mt * 16 + (lane & 15);
                int ch  = ks * 2 + (lane >> 4);
                ldsm4(ah[mt], sA + row * 128 + ((ch ^ (row & 7)) << 4));
            }
            int rowb = ks * 16 + (lane & 7) + ((lane >> 4) << 3);
            int chs  = (lane >> 3) & 1;
            int rx   = rowb & 7;
            uint32_t rowoff = rowb * 256;
            uint32_t bh[4][2];
            #pragma unroll
            for (int p = 0; p < 2; p++) {
                int ch = ((wn + p * 16) >> 3) + chs;
                uint32_t r[4];
                ldsm4t(r, sB + rowoff + ((ch ^ rx) << 4));
                bh[2*p][0] = r[0];   bh[2*p][1] = r[2];
                bh[2*p+1][0] = r[1]; bh[2*p+1][1] = r[3];
            }
            #pragma unroll
            for (int mt = 0; mt < 4; mt++)
                #pragma unroll
                for (int nt = 0; nt < 4; nt++)
                    mma_f16(acc[mt][nt], ah[mt], bh[nt]);
        }
        __syncthreads();
        if (kt < 2)
            fill(sb + (kt & 1) * 32768, (kt + 2) * 64);
        CP_COMMIT();
    }

    float* ob = out + (size_t)b * C_ * SEQ_;
    #pragma unroll
    for (int nt = 0; nt < 4; nt++) {
        int c = n0 + wn + nt * 8 + 2 * tg;
        float b0f = bo[c], b1f = bo[c + 1];
        #pragma unroll
        for (int mt = 0; mt < 4; mt++) {
            int s = s0 + wm + mt * 16 + g;
            ob[(size_t)c       * SEQ_ + s]     = acc[mt][nt][0] + b0f;
            ob[(size_t)(c + 1) * SEQ_ + s]     = acc[mt][nt][1] + b1f;
            ob[(size_t)c       * SEQ_ + s + 8] = acc[mt][nt][2] + b0f;
            ob[(size_t)(c + 1) * SEQ_ + s + 8] = acc[mt][nt][3] + b1f;
        }
    }
}

// ============================================================================
extern "C" void kernel_launch(void* const* d_in, const int* in_sizes, int n_in,
                              void* d_out, int out_size)
{
    const float* x   = (const float*)d_in[0];
    const float* wq  = (const float*)d_in[1];
    const float* bq  = (const float*)d_in[2];
    const float* wkv = (const float*)d_in[3];
    const float* bkv = (const float*)d_in[4];
    const float* wo  = (const float*)d_in[5];
    const float* bo  = (const float*)d_in[6];
    float* out = (float*)d_out;

    static cudaStream_t s[2];
    static cudaEvent_t evFork, evJoin[2];
    static bool init_done = false;
    if (!init_done) {
        cudaFuncSetAttribute(gemm_qkv_mma,
            cudaFuncAttributeMaxDynamicSharedMemorySize, 2 * G1_ST);
        cudaFuncSetAttribute(gemm_out_mma,
            cudaFuncAttributeMaxDynamicSharedMemorySize, 65536);
        cudaStreamCreateWithFlags(&s[0], cudaStreamNonBlocking);
        cudaStreamCreateWithFlags(&s[1], cudaStreamNonBlocking);
        cudaEventCreateWithFlags(&evFork,    cudaEventDisableTiming);
        cudaEventCreateWithFlags(&evJoin[0], cudaEventDisableTiming);
        cudaEventCreateWithFlags(&evJoin[1], cudaEventDisableTiming);
        init_done = true;
    }

    __half *woh;
    cudaGetSymbolAddress((void**)&woh, g_woh);

    // small weight convs on the capture (default) stream
    int nw4 = (C_ * C_) / 4;
    conv_f4<<<(nw4 + 255) / 256, 256>>>((const float4*)wo, (uint2*)woh, nw4);
    conv_wqkv<<<(C_ * NQKV) / 256, 256>>>(wq, wkv);

    // fork two non-blocking streams off the capture stream
    cudaEventRecord(evFork, 0);
    cudaStreamWaitEvent(s[0], evFork, 0);
    cudaStreamWaitEvent(s[1], evFork, 0);

    // one chain per stream: GEMM1(g, fused x-conv) -> attn(g) -> GEMM2(g)
    for (int gidx = 0; gidx < NGRP; gidx++) {
        cudaStream_t st = s[gidx & 1];
        int b0 = gidx * GRP;
        gemm_qkv_mma<<<dim3(6, 32, GRP), 256, 2 * G1_ST, st>>>(x, bq, bkv, b0);
        attn_kernel<<<(GRP * SEQ_) / 8, 256, 0, st>>>(b0);
        gemm_out_mma<<<dim3(2, 32, GRP), 256, 65536, st>>>(bo, out, b0);
    }

    // join back to the capture stream
    cudaEventRecord(evJoin[0], s[0]);
    cudaEventRecord(evJoin[1], s[1]);
    cudaStreamWaitEvent(0, evJoin[0], 0);
    cudaStreamWaitEvent(0, evJoin[1], 0);
}